// round 1
// baseline (speedup 1.0000x reference)
#include <cuda_runtime.h>

// Problem constants (from reference): B=32, T=168, M=1024, A=8, H=64, O=1
#define Mu   1024
#define Au   8
#define Hu   64

// Coefficient table: per map-unit m we store
//   [m*3+0] = (u0,u1,u2,u3)
//   [m*3+1] = (u4,u5,u6,u7)
//   [m*3+2] = (c_mn, c_mx, c_const, 0)
// where u[a]   = sum_h assoc_w[m,a,h] * dense_w[m,h]
//       v      = sum_h assoc_b[m,h]   * dense_w[m,h]
//       s      = sum_h dense_w[m,h]
//       U      = sum_a u[a]
//       c_mn   = s - U - v
//       c_mx   = v
//       c_const= dense_b[m]
// Then out = dot(xt, u) + mn*c_mn + mx*c_mx + c_const
// which equals the reference's
//   sum_a (xt[a]-mn)*u[a] + (mx-mn)*v + mn*s + db  (LSTM state is dead code).
__device__ float4 g_coef[Mu * 3];

__device__ __forceinline__ float warp_sum(float v) {
    #pragma unroll
    for (int off = 16; off > 0; off >>= 1)
        v += __shfl_down_sync(0xffffffffu, v, off);
    return v;
}

__global__ void precompute_kernel(const float* __restrict__ assoc_w,   // [M,A,H]
                                  const float* __restrict__ assoc_b,   // [M,H]
                                  const float* __restrict__ dense_w,   // [M,H,1]
                                  const float* __restrict__ dense_b) { // [M,1]
    const int m = blockIdx.x;        // 1024 blocks
    const int h = threadIdx.x;       // 64 threads
    const int w = h >> 5;            // warp id (0/1)
    const int lane = h & 31;

    const float d  = dense_w[m * Hu + h];
    const float ab = assoc_b[m * Hu + h];

    float vals[10];
    #pragma unroll
    for (int a = 0; a < Au; a++)
        vals[a] = assoc_w[((size_t)m * Au + a) * Hu + h] * d;   // u[a] partial
    vals[8] = ab * d;   // v partial
    vals[9] = d;        // s partial

    __shared__ float sh[10][2];
    #pragma unroll
    for (int i = 0; i < 10; i++) {
        float r = warp_sum(vals[i]);
        if (lane == 0) sh[i][w] = r;
    }
    __syncthreads();

    if (h == 0) {
        float u[8], v, s, U = 0.0f;
        #pragma unroll
        for (int a = 0; a < 8; a++) { u[a] = sh[a][0] + sh[a][1]; U += u[a]; }
        v = sh[8][0] + sh[8][1];
        s = sh[9][0] + sh[9][1];
        g_coef[m * 3 + 0] = make_float4(u[0], u[1], u[2], u[3]);
        g_coef[m * 3 + 1] = make_float4(u[4], u[5], u[6], u[7]);
        g_coef[m * 3 + 2] = make_float4(s - U - v, v, dense_b[m], 0.0f);
    }
}

__global__ void __launch_bounds__(256)
fused_kernel(const float* __restrict__ x,   // [B,T,M,A] contiguous
             float* __restrict__ out,       // [B,T,M]
             int n) {                       // n = B*T*M
    const int idx = blockIdx.x * blockDim.x + threadIdx.x;
    if (idx >= n) return;

    const int m = idx & (Mu - 1);           // M = 1024 (power of 2), fastest dim

    // 8 contiguous attrs -> two 16B vector loads (32B aligned: idx*32 bytes)
    const float4* xp = reinterpret_cast<const float4*>(x) + (size_t)idx * 2;
    const float4 a = __ldg(xp);
    const float4 b = __ldg(xp + 1);

    float mn = fminf(fminf(fminf(a.x, a.y), fminf(a.z, a.w)),
                     fminf(fminf(b.x, b.y), fminf(b.z, b.w)));
    float mx = fmaxf(fmaxf(fmaxf(a.x, a.y), fmaxf(a.z, a.w)),
                     fmaxf(fmaxf(b.x, b.y), fmaxf(b.z, b.w)));

    const float4 u0 = g_coef[m * 3 + 0];
    const float4 u1 = g_coef[m * 3 + 1];
    const float4 c  = g_coef[m * 3 + 2];

    float dot = a.x * u0.x + a.y * u0.y + a.z * u0.z + a.w * u0.w
              + b.x * u1.x + b.y * u1.y + b.z * u1.z + b.w * u1.w;

    out[idx] = dot + mn * c.x + mx * c.y + c.z;
}

extern "C" void kernel_launch(void* const* d_in, const int* in_sizes, int n_in,
                              void* d_out, int out_size) {
    // metadata order: input, assoc_w, assoc_b, w_ih, w_hh, b_ih, b_hh, dense_w, dense_b
    const float* x        = (const float*)d_in[0];
    const float* assoc_w  = (const float*)d_in[1];
    const float* assoc_b  = (const float*)d_in[2];
    const float* dense_w  = (const float*)d_in[7];
    const float* dense_b  = (const float*)d_in[8];
    float* out            = (float*)d_out;

    precompute_kernel<<<Mu, Hu>>>(assoc_w, assoc_b, dense_w, dense_b);

    const int n = out_size;                 // B*T*M = 5,505,024
    const int threads = 256;
    const int blocks = (n + threads - 1) / threads;
    fused_kernel<<<blocks, threads>>>(x, out, n);
}

// round 2
// speedup vs baseline: 1.0522x; 1.0522x over previous
#include <cuda_runtime.h>

// Problem constants (from reference): B=32, T=168, M=1024, A=8, H=64, O=1
#define Mu   1024
#define Au   8
#define Hu   64

// Coefficient table: per map-unit m we store
//   [m*3+0] = (u0,u1,u2,u3)
//   [m*3+1] = (u4,u5,u6,u7)
//   [m*3+2] = (c_mn, c_mx, c_const, 0)
// where u[a]   = sum_h assoc_w[m,a,h] * dense_w[m,h]
//       v      = sum_h assoc_b[m,h]   * dense_w[m,h]
//       s      = sum_h dense_w[m,h]
//       U      = sum_a u[a]
//       c_mn   = s - U - v ;  c_mx = v ;  c_const = dense_b[m]
// out = dot(xt,u) + mn*c_mn + mx*c_mx + c_const   (LSTM state is dead code;
// the /(mx-mn) and *(mx-mn) cancel algebraically).
__device__ float4 g_coef[Mu * 3];

__device__ __forceinline__ float warp_sum(float v) {
    #pragma unroll
    for (int off = 16; off > 0; off >>= 1)
        v += __shfl_xor_sync(0xffffffffu, v, off);
    return v;
}

// One warp per map-unit m. Each lane covers 2 h-values via float2 loads.
// 8 warps/block -> 128 blocks. All 10 reductions run with full ILP.
__global__ void __launch_bounds__(256)
precompute_kernel(const float* __restrict__ assoc_w,   // [M,A,H]
                  const float* __restrict__ assoc_b,   // [M,H]
                  const float* __restrict__ dense_w,   // [M,H]
                  const float* __restrict__ dense_b) { // [M]
    const int warp = threadIdx.x >> 5;
    const int lane = threadIdx.x & 31;
    const int m = blockIdx.x * 8 + warp;   // grid = 128, 8 warps/block

    const float2 d  = reinterpret_cast<const float2*>(dense_w + m * Hu)[lane];
    const float2 ab = reinterpret_cast<const float2*>(assoc_b + m * Hu)[lane];

    float vals[10];
    #pragma unroll
    for (int a = 0; a < Au; a++) {
        const float2 w = reinterpret_cast<const float2*>(
            assoc_w + ((size_t)m * Au + a) * Hu)[lane];
        vals[a] = w.x * d.x + w.y * d.y;
    }
    vals[8] = ab.x * d.x + ab.y * d.y;   // v partial
    vals[9] = d.x + d.y;                  // s partial

    #pragma unroll
    for (int i = 0; i < 10; i++)
        vals[i] = warp_sum(vals[i]);

    if (lane == 0) {
        float U = vals[0] + vals[1] + vals[2] + vals[3]
                + vals[4] + vals[5] + vals[6] + vals[7];
        g_coef[m * 3 + 0] = make_float4(vals[0], vals[1], vals[2], vals[3]);
        g_coef[m * 3 + 1] = make_float4(vals[4], vals[5], vals[6], vals[7]);
        g_coef[m * 3 + 2] = make_float4(vals[9] - U - vals[8], vals[8],
                                        dense_b[m], 0.0f);
    }
}

// 2 elements per thread, stride = n/2. n/2 = 2688*1024 is a multiple of M,
// so both elements share the same m -> coefficient registers reused, and
// 4 independent LDG.128 in flight per thread (MLP_p1 = 4).
__global__ void __launch_bounds__(256)
fused_kernel(const float* __restrict__ x,   // [B,T,M,A] contiguous
             float* __restrict__ out,       // [B,T,M]
             int half) {                    // half = B*T*M / 2
    const int idx = blockIdx.x * blockDim.x + threadIdx.x;
    if (idx >= half) return;

    const int m = idx & (Mu - 1);           // M = 1024, fastest dim

    const float4* xp0 = reinterpret_cast<const float4*>(x) + (size_t)idx * 2;
    const float4* xp1 = xp0 + (size_t)half * 2;

    // issue all 4 streaming loads up front
    const float4 a0 = __ldcs(xp0);
    const float4 b0 = __ldcs(xp0 + 1);
    const float4 a1 = __ldcs(xp1);
    const float4 b1 = __ldcs(xp1 + 1);

    const float4 u0 = g_coef[m * 3 + 0];
    const float4 u1 = g_coef[m * 3 + 1];
    const float4 c  = g_coef[m * 3 + 2];

    float mn0 = fminf(fminf(fminf(a0.x, a0.y), fminf(a0.z, a0.w)),
                      fminf(fminf(b0.x, b0.y), fminf(b0.z, b0.w)));
    float mx0 = fmaxf(fmaxf(fmaxf(a0.x, a0.y), fmaxf(a0.z, a0.w)),
                      fmaxf(fmaxf(b0.x, b0.y), fmaxf(b0.z, b0.w)));
    float dot0 = a0.x * u0.x + a0.y * u0.y + a0.z * u0.z + a0.w * u0.w
               + b0.x * u1.x + b0.y * u1.y + b0.z * u1.z + b0.w * u1.w;

    float mn1 = fminf(fminf(fminf(a1.x, a1.y), fminf(a1.z, a1.w)),
                      fminf(fminf(b1.x, b1.y), fminf(b1.z, b1.w)));
    float mx1 = fmaxf(fmaxf(fmaxf(a1.x, a1.y), fmaxf(a1.z, a1.w)),
                      fmaxf(fmaxf(b1.x, b1.y), fmaxf(b1.z, b1.w)));
    float dot1 = a1.x * u0.x + a1.y * u0.y + a1.z * u0.z + a1.w * u0.w
               + b1.x * u1.x + b1.y * u1.y + b1.z * u1.z + b1.w * u1.w;

    __stcs(out + idx,        dot0 + mn0 * c.x + mx0 * c.y + c.z);
    __stcs(out + idx + half, dot1 + mn1 * c.x + mx1 * c.y + c.z);
}

extern "C" void kernel_launch(void* const* d_in, const int* in_sizes, int n_in,
                              void* d_out, int out_size) {
    // metadata order: input, assoc_w, assoc_b, w_ih, w_hh, b_ih, b_hh, dense_w, dense_b
    const float* x        = (const float*)d_in[0];
    const float* assoc_w  = (const float*)d_in[1];
    const float* assoc_b  = (const float*)d_in[2];
    const float* dense_w  = (const float*)d_in[7];
    const float* dense_b  = (const float*)d_in[8];
    float* out            = (float*)d_out;

    precompute_kernel<<<Mu / 8, 256>>>(assoc_w, assoc_b, dense_w, dense_b);

    const int half = out_size / 2;          // 2,752,512 (multiple of 1024)
    const int threads = 256;
    const int blocks = (half + threads - 1) / threads;  // 10752
    fused_kernel<<<blocks, threads>>>(x, out, half);
}

// round 3
// speedup vs baseline: 1.0571x; 1.0047x over previous
#include <cuda_runtime.h>

// Problem constants (from reference): B=32, T=168, M=1024, A=8, H=64, O=1
#define Mu   1024
#define Au   8
#define Hu   64

// Coefficient table: per map-unit m we store
//   [m*3+0] = (u0,u1,u2,u3)
//   [m*3+1] = (u4,u5,u6,u7)
//   [m*3+2] = (c_mn, c_mx, c_const, 0)
// where u[a]   = sum_h assoc_w[m,a,h] * dense_w[m,h]
//       v      = sum_h assoc_b[m,h]   * dense_w[m,h]
//       s      = sum_h dense_w[m,h]
//       U      = sum_a u[a]
//       c_mn   = s - U - v ;  c_mx = v ;  c_const = dense_b[m]
// out = dot(xt,u) + mn*c_mn + mx*c_mx + c_const   (LSTM state is dead code;
// the /(mx-mn) and *(mx-mn) cancel algebraically).
__device__ float4 g_coef[Mu * 3];

__device__ __forceinline__ float warp_sum(float v) {
    #pragma unroll
    for (int off = 16; off > 0; off >>= 1)
        v += __shfl_xor_sync(0xffffffffu, v, off);
    return v;
}

// One warp per map-unit m. Each lane covers 2 h-values via float2 loads.
// 8 warps/block -> 128 blocks. All 10 reductions run with full ILP.
__global__ void __launch_bounds__(256)
precompute_kernel(const float* __restrict__ assoc_w,   // [M,A,H]
                  const float* __restrict__ assoc_b,   // [M,H]
                  const float* __restrict__ dense_w,   // [M,H]
                  const float* __restrict__ dense_b) { // [M]
    const int warp = threadIdx.x >> 5;
    const int lane = threadIdx.x & 31;
    const int m = blockIdx.x * 8 + warp;   // grid = 128, 8 warps/block

    const float2 d  = reinterpret_cast<const float2*>(dense_w + m * Hu)[lane];
    const float2 ab = reinterpret_cast<const float2*>(assoc_b + m * Hu)[lane];

    float vals[10];
    #pragma unroll
    for (int a = 0; a < Au; a++) {
        const float2 w = reinterpret_cast<const float2*>(
            assoc_w + ((size_t)m * Au + a) * Hu)[lane];
        vals[a] = w.x * d.x + w.y * d.y;
    }
    vals[8] = ab.x * d.x + ab.y * d.y;   // v partial
    vals[9] = d.x + d.y;                 // s partial

    #pragma unroll
    for (int i = 0; i < 10; i++)
        vals[i] = warp_sum(vals[i]);

    if (lane == 0) {
        float U = vals[0] + vals[1] + vals[2] + vals[3]
                + vals[4] + vals[5] + vals[6] + vals[7];
        g_coef[m * 3 + 0] = make_float4(vals[0], vals[1], vals[2], vals[3]);
        g_coef[m * 3 + 1] = make_float4(vals[4], vals[5], vals[6], vals[7]);
        g_coef[m * 3 + 2] = make_float4(vals[9] - U - vals[8], vals[8],
                                        dense_b[m], 0.0f);
    }
}

// 1 element per thread (R1 shape: regs=30, occ~70%, DRAM 79%).
// Streaming hints: x/out are touched exactly once -> evict-first, which
// protects the 48KB coefficient table in L1/L2.
__global__ void __launch_bounds__(256)
fused_kernel(const float* __restrict__ x,   // [B,T,M,A] contiguous
             float* __restrict__ out,       // [B,T,M]
             int n) {                       // n = B*T*M
    const int idx = blockIdx.x * blockDim.x + threadIdx.x;
    if (idx >= n) return;

    const int m = idx & (Mu - 1);           // M = 1024 (power of 2), fastest dim

    const float4* xp = reinterpret_cast<const float4*>(x) + (size_t)idx * 2;
    const float4 a = __ldcs(xp);
    const float4 b = __ldcs(xp + 1);

    float mn = fminf(fminf(fminf(a.x, a.y), fminf(a.z, a.w)),
                     fminf(fminf(b.x, b.y), fminf(b.z, b.w)));
    float mx = fmaxf(fmaxf(fmaxf(a.x, a.y), fmaxf(a.z, a.w)),
                     fmaxf(fmaxf(b.x, b.y), fmaxf(b.z, b.w)));

    const float4 u0 = g_coef[m * 3 + 0];
    const float4 u1 = g_coef[m * 3 + 1];
    const float4 c  = g_coef[m * 3 + 2];

    float dot = a.x * u0.x + a.y * u0.y + a.z * u0.z + a.w * u0.w
              + b.x * u1.x + b.y * u1.y + b.z * u1.z + b.w * u1.w;

    __stcs(out + idx, dot + mn * c.x + mx * c.y + c.z);
}

extern "C" void kernel_launch(void* const* d_in, const int* in_sizes, int n_in,
                              void* d_out, int out_size) {
    // metadata order: input, assoc_w, assoc_b, w_ih, w_hh, b_ih, b_hh, dense_w, dense_b
    const float* x        = (const float*)d_in[0];
    const float* assoc_w  = (const float*)d_in[1];
    const float* assoc_b  = (const float*)d_in[2];
    const float* dense_w  = (const float*)d_in[7];
    const float* dense_b  = (const float*)d_in[8];
    float* out            = (float*)d_out;

    precompute_kernel<<<Mu / 8, 256>>>(assoc_w, assoc_b, dense_w, dense_b);

    const int n = out_size;                 // B*T*M = 5,505,024
    const int threads = 256;
    const int blocks = (n + threads - 1) / threads;  // 21504
    fused_kernel<<<blocks, threads>>>(x, out, n);
}

// round 4
// speedup vs baseline: 1.0856x; 1.0269x over previous
#include <cuda_runtime.h>

// Problem constants (from reference): B=32, T=168, M=1024, A=8, H=64, O=1
#define Mu   1024
#define Au   8
#define Hu   64

// Coefficient table: per map-unit m we store
//   [m*3+0] = (u0,u1,u2,u3)
//   [m*3+1] = (u4,u5,u6,u7)
//   [m*3+2] = (c_mn, c_mx, c_const, 0)
// where u[a]   = sum_h assoc_w[m,a,h] * dense_w[m,h]
//       v      = sum_h assoc_b[m,h]   * dense_w[m,h]
//       s      = sum_h dense_w[m,h]
//       U      = sum_a u[a]
//       c_mn   = s - U - v ;  c_mx = v ;  c_const = dense_b[m]
// out = dot(xt,u) + mn*c_mn + mx*c_mx + c_const   (LSTM state is dead code;
// the /(mx-mn) and *(mx-mn) cancel algebraically).
__device__ float4 g_coef[Mu * 3];

__device__ __forceinline__ float warp_sum(float v) {
    #pragma unroll
    for (int off = 16; off > 0; off >>= 1)
        v += __shfl_xor_sync(0xffffffffu, v, off);
    return v;
}

// One warp per map-unit m. Each lane covers 2 h-values via float2 loads.
// 8 warps/block -> 128 blocks. All 10 reductions run with full ILP.
// Calls the PDL trigger after its g_coef stores so the fused kernel's
// grid can begin launching (and prefetching x) while this kernel drains.
__global__ void __launch_bounds__(256)
precompute_kernel(const float* __restrict__ assoc_w,   // [M,A,H]
                  const float* __restrict__ assoc_b,   // [M,H]
                  const float* __restrict__ dense_w,   // [M,H]
                  const float* __restrict__ dense_b) { // [M]
    const int warp = threadIdx.x >> 5;
    const int lane = threadIdx.x & 31;
    const int m = blockIdx.x * 8 + warp;   // grid = 128, 8 warps/block

    const float2 d  = reinterpret_cast<const float2*>(dense_w + m * Hu)[lane];
    const float2 ab = reinterpret_cast<const float2*>(assoc_b + m * Hu)[lane];

    float vals[10];
    #pragma unroll
    for (int a = 0; a < Au; a++) {
        const float2 w = reinterpret_cast<const float2*>(
            assoc_w + ((size_t)m * Au + a) * Hu)[lane];
        vals[a] = w.x * d.x + w.y * d.y;
    }
    vals[8] = ab.x * d.x + ab.y * d.y;   // v partial
    vals[9] = d.x + d.y;                 // s partial

    #pragma unroll
    for (int i = 0; i < 10; i++)
        vals[i] = warp_sum(vals[i]);

    if (lane == 0) {
        float U = vals[0] + vals[1] + vals[2] + vals[3]
                + vals[4] + vals[5] + vals[6] + vals[7];
        g_coef[m * 3 + 0] = make_float4(vals[0], vals[1], vals[2], vals[3]);
        g_coef[m * 3 + 1] = make_float4(vals[4], vals[5], vals[6], vals[7]);
        g_coef[m * 3 + 2] = make_float4(vals[9] - U - vals[8], vals[8],
                                        dense_b[m], 0.0f);
    }

    // All g_coef writes in this block precede the trigger -> visible to the
    // secondary kernel after its cudaGridDependencySynchronize().
    cudaTriggerProgrammaticLaunchCompletion();
}

// 1 element per thread (regs=30, occ~74%, DRAM 78%).
// PDL secondary: prefetch the streaming x loads, THEN wait on the primary
// before touching g_coef. x/out get streaming (evict-first) hints.
__global__ void __launch_bounds__(256)
fused_kernel(const float* __restrict__ x,   // [B,T,M,A] contiguous
             float* __restrict__ out,       // [B,T,M]
             int n) {                       // n = B*T*M
    const int idx = blockIdx.x * blockDim.x + threadIdx.x;
    if (idx >= n) return;

    const int m = idx & (Mu - 1);           // M = 1024 (power of 2), fastest dim

    const float4* xp = reinterpret_cast<const float4*>(x) + (size_t)idx * 2;
    const float4 a = __ldcs(xp);            // issued before the dependency wait
    const float4 b = __ldcs(xp + 1);

    cudaGridDependencySynchronize();        // g_coef now valid

    float mn = fminf(fminf(fminf(a.x, a.y), fminf(a.z, a.w)),
                     fminf(fminf(b.x, b.y), fminf(b.z, b.w)));
    float mx = fmaxf(fmaxf(fmaxf(a.x, a.y), fmaxf(a.z, a.w)),
                     fmaxf(fmaxf(b.x, b.y), fmaxf(b.z, b.w)));

    const float4 u0 = g_coef[m * 3 + 0];
    const float4 u1 = g_coef[m * 3 + 1];
    const float4 c  = g_coef[m * 3 + 2];

    float dot = a.x * u0.x + a.y * u0.y + a.z * u0.z + a.w * u0.w
              + b.x * u1.x + b.y * u1.y + b.z * u1.z + b.w * u1.w;

    __stcs(out + idx, dot + mn * c.x + mx * c.y + c.z);
}

extern "C" void kernel_launch(void* const* d_in, const int* in_sizes, int n_in,
                              void* d_out, int out_size) {
    // metadata order: input, assoc_w, assoc_b, w_ih, w_hh, b_ih, b_hh, dense_w, dense_b
    const float* x        = (const float*)d_in[0];
    const float* assoc_w  = (const float*)d_in[1];
    const float* assoc_b  = (const float*)d_in[2];
    const float* dense_w  = (const float*)d_in[7];
    const float* dense_b  = (const float*)d_in[8];
    float* out            = (float*)d_out;

    precompute_kernel<<<Mu / 8, 256>>>(assoc_w, assoc_b, dense_w, dense_b);

    const int n = out_size;                 // B*T*M = 5,505,024
    const int threads = 256;
    const int blocks = (n + threads - 1) / threads;  // 21504

    // Launch fused kernel with programmatic stream serialization (PDL):
    // its blocks may begin before precompute fully completes; the device-side
    // cudaGridDependencySynchronize() provides the actual ordering on g_coef.
    cudaLaunchConfig_t cfg = {};
    cfg.gridDim  = dim3(blocks, 1, 1);
    cfg.blockDim = dim3(threads, 1, 1);
    cfg.dynamicSmemBytes = 0;
    cfg.stream = 0;
    cudaLaunchAttribute attr[1];
    attr[0].id = cudaLaunchAttributeProgrammaticStreamSerialization;
    attr[0].val.programmaticStreamSerializationAllowed = 1;
    cfg.attrs = attr;
    cfg.numAttrs = 1;
    cudaLaunchKernelEx(&cfg, fused_kernel, x, out, n);
}